// round 10
// baseline (speedup 1.0000x reference)
#include <cuda_runtime.h>
#include <cstdint>
#include <math.h>

// ---------------- problem constants ----------------
constexpr int B        = 16384;
constexpr int NM       = 64;
constexpr int IN_F     = 6;
constexpr int OUT_F    = 3;
constexpr int HID      = 128;
constexpr int NFACT    = 4;

constexpr int MT       = 64;    // elements per tile (MMA M)
constexpr int XP       = 132;   // smem pitch (floats)
constexpr int NTHREADS = 128;   // 4 warps x 16 rows = 64 elements
constexpr int NT_X     = 4;     // CTA stride over tiles of one (model, factor)

constexpr int OFF_IDX  = B * NFACT * OUT_F;
constexpr int OFF_LOG  = OFF_IDX + B;
constexpr int OFF_PROB = OFF_LOG + B * NM;

#define DINL __device__ __forceinline__

// ---------------- device scratch ----------------
__device__ int g_idx[B];
__device__ int g_counts[NM];
__device__ int g_offsets[NM + 1];
__device__ int g_cursor[NM];
__device__ int g_order[B];

// ---------------- prologue kernels ----------------
__global__ void k_zero() {
    if (threadIdx.x < NM) g_counts[threadIdx.x] = 0;
}

// select model index + indices output + logits/probs fill (merged)
__global__ void k_select(const float* __restrict__ inp, float* __restrict__ out) {
    __shared__ int h[NM];
    if (threadIdx.x < NM) h[threadIdx.x] = 0;
    __syncthreads();

    int b = blockIdx.x * blockDim.x + threadIdx.x;   // grid covers exactly B
    float x0 = inp[b * 6 + 0];
    float x2 = inp[b * 6 + 2];
    const float TPf = 6.2831853071795864769f;
    float ang = (float)atan2((double)x2, (double)x0); // correctly-rounded f32 atan2
    float t   = ang + TPf;
    float a   = fmodf(t, TPf);
    float v   = a / TPf * 64.0f;
    int idx = (int)floorf(v);
    idx = max(0, min(63, idx));

    g_idx[b] = idx;
    out[OFF_IDX + b] = (float)idx;

    atomicAdd(&h[idx], 1);

    // fill logits (1.0) and probabilities (1/64): 16 float4 each per thread
    float4 ones = make_float4(1.f, 1.f, 1.f, 1.f);
    float4 prob = make_float4(0.015625f, 0.015625f, 0.015625f, 0.015625f);
    float4* lg = (float4*)(out + OFF_LOG) + (size_t)b * 16;
    float4* pb = (float4*)(out + OFF_PROB) + (size_t)b * 16;
    #pragma unroll
    for (int i = 0; i < 16; ++i) { lg[i] = ones; pb[i] = prob; }

    __syncthreads();
    if (threadIdx.x < NM && h[threadIdx.x]) atomicAdd(&g_counts[threadIdx.x], h[threadIdx.x]);
}

__global__ void k_scan() {
    int t = threadIdx.x;
    int c = g_counts[t];
    int v = c;
    #pragma unroll
    for (int d = 1; d < 32; d <<= 1) {
        int n = __shfl_up_sync(0xFFFFFFFFu, v, d);
        if ((t & 31) >= d) v += n;
    }
    __shared__ int ws[2];
    if ((t & 31) == 31) ws[t >> 5] = v;
    __syncthreads();
    if (t >= 32) v += ws[0];
    g_offsets[t + 1] = v;
    if (t == 0) g_offsets[0] = 0;
    g_cursor[t] = v - c;
}

__global__ void k_scatter() {
    int b = blockIdx.x * blockDim.x + threadIdx.x;
    int idx = g_idx[b];
    int pos = atomicAdd(&g_cursor[idx], 1);
    g_order[pos] = b;
}

// ---------------- tf32 helpers ----------------
DINL uint32_t tf32u(float x) {
    uint32_t r;
    asm("cvt.rna.tf32.f32 %0, %1;" : "=r"(r) : "f"(x));
    return r;
}
DINL float tf32f(float x) { return __uint_as_float(tf32u(x)); }

// mma.sync m16n8k8 tf32 fp32-acc, accumulate in place
DINL void mma8(float& c0, float& c1, float& c2, float& c3,
               uint32_t a0, uint32_t a1, uint32_t a2, uint32_t a3,
               uint32_t b0, uint32_t b1) {
    asm volatile(
        "mma.sync.aligned.m16n8k8.row.col.f32.tf32.tf32.f32 "
        "{%0,%1,%2,%3}, {%4,%5,%6,%7}, {%8,%9}, {%0,%1,%2,%3};"
        : "+f"(c0), "+f"(c1), "+f"(c2), "+f"(c3)
        : "r"(a0), "r"(a1), "r"(a2), "r"(a3), "r"(b0), "r"(b1));
}

// ---------------- fused FC layer (in-place X), paired-K weights ----------------
// Fragment mapping (m16n8k8.row.col), g=lane>>2, tig=lane&3:
//   A: a0=(g,tig) a1=(g+8,tig) a2=(g,tig+4) a3=(g+8,tig+4)    [plain X layout]
//   B: b0=(k=tig,n) b1=(k=tig+4,n) -> paired Ws layout: one float2
//   D: c0=(g,2tig) c1=(g,2tig+1) c2=(g+8,2tig) c3=(g+8,2tig+1)
// In-place safety: all KC A-fragments preloaded to regs (+syncwarp) before any store;
// warps own disjoint 16-row slices.
template<int KC, int NC>
DINL void layer_fc(float* __restrict__ X, const float* __restrict__ Ws,
                   const float* __restrict__ Bs, int e0, int g, int tig) {
    uint32_t a[KC][4];
    #pragma unroll
    for (int kc = 0; kc < KC; ++kc) {
        const float* xr = X + (e0 + g) * XP + kc * 8 + tig;
        a[kc][0] = __float_as_uint(xr[0]);
        a[kc][2] = __float_as_uint(xr[4]);
        a[kc][1] = __float_as_uint(xr[8 * XP]);
        a[kc][3] = __float_as_uint(xr[8 * XP + 4]);
    }
    __syncwarp();

    #pragma unroll
    for (int nc = 0; nc < NC; nc += 4) {
        float c[4][4];
        #pragma unroll
        for (int q = 0; q < 4; ++q) {
            float2 bi = *(const float2*)(Bs + (nc + q) * 8 + 2 * tig);
            c[q][0] = bi.x; c[q][1] = bi.y; c[q][2] = bi.x; c[q][3] = bi.y;
        }
        #pragma unroll
        for (int kc = 0; kc < KC; ++kc) {
            #pragma unroll
            for (int q = 0; q < 4; ++q) {
                float2 w = *(const float2*)(Ws + ((nc + q) * 8 + g) * XP + kc * 8 + 2 * tig);
                mma8(c[q][0], c[q][1], c[q][2], c[q][3],
                     a[kc][0], a[kc][1], a[kc][2], a[kc][3],
                     __float_as_uint(w.x), __float_as_uint(w.y));
            }
        }
        #pragma unroll
        for (int q = 0; q < 4; ++q) {
            const int n0 = (nc + q) * 8;
            float2 v;
            v.x = tf32f(fmaxf(c[q][0], 0.f)); v.y = tf32f(fmaxf(c[q][1], 0.f));
            *(float2*)(X + (e0 + g) * XP + n0 + 2 * tig) = v;
            v.x = tf32f(fmaxf(c[q][2], 0.f)); v.y = tf32f(fmaxf(c[q][3], 0.f));
            *(float2*)(X + (e0 + 8 + g) * XP + n0 + 2 * tig) = v;
        }
    }
}

// output layer: N=8 (3 valid), no relu, direct gmem store
template<int KC>
DINL void layer_out(const float* __restrict__ X, const float* __restrict__ Ws,
                    const float* __restrict__ Bs, float* __restrict__ out,
                    const int* __restrict__ ords, int cnt, int fi,
                    int e0, int g, int tig) {
    uint32_t a[KC][4];
    #pragma unroll
    for (int kc = 0; kc < KC; ++kc) {
        const float* xr = X + (e0 + g) * XP + kc * 8 + tig;
        a[kc][0] = __float_as_uint(xr[0]);
        a[kc][2] = __float_as_uint(xr[4]);
        a[kc][1] = __float_as_uint(xr[8 * XP]);
        a[kc][3] = __float_as_uint(xr[8 * XP + 4]);
    }
    float c0 = Bs[2 * tig], c1 = Bs[2 * tig + 1];
    float c2 = c0, c3 = c1;
    #pragma unroll
    for (int kc = 0; kc < KC; ++kc) {
        float2 w = *(const float2*)(Ws + g * XP + kc * 8 + 2 * tig);
        mma8(c0, c1, c2, c3, a[kc][0], a[kc][1], a[kc][2], a[kc][3],
             __float_as_uint(w.x), __float_as_uint(w.y));
    }
    const int col0 = 2 * tig, col1 = 2 * tig + 1;
    const int e1 = e0 + g, e2 = e0 + 8 + g;
    if (e1 < cnt) {
        const int base = ords[e1] * (NFACT * OUT_F) + fi * OUT_F;
        if (col0 < OUT_F) out[base + col0] = c0;
        if (col1 < OUT_F) out[base + col1] = c1;
    }
    if (e2 < cnt) {
        const int base = ords[e2] * (NFACT * OUT_F) + fi * OUT_F;
        if (col0 < OUT_F) out[base + col0] = c2;
        if (col1 < OUT_F) out[base + col1] = c3;
    }
}

// ---------------- staging (paired-K layout, tf32-rounded) ----------------
// Ws[n*XP + kc*8 + 2c+h] = tf32(W[n][kc*8 + c + 4h]),  c=0..3, h=0..1
template<int H>
DINL void stage_wh(const float* __restrict__ Wg, float* __restrict__ Ws) {
    constexpr int KCH = H / 8;
    for (int i = threadIdx.x; i < H * KCH; i += NTHREADS) {
        int n = i / KCH, kc = i - n * KCH;
        const float* src = Wg + n * HID + kc * 8;
        float4 w = *(const float4*)(src);
        float4 v = *(const float4*)(src + 4);
        float* dst = Ws + n * XP + kc * 8;
        *(float4*)(dst)     = make_float4(tf32f(w.x), tf32f(v.x), tf32f(w.y), tf32f(v.y));
        *(float4*)(dst + 4) = make_float4(tf32f(w.z), tf32f(v.z), tf32f(w.w), tf32f(v.w));
    }
}
template<int H>
DINL void stage_w0(const float* __restrict__ Wg, float* __restrict__ Ws) {
    for (int n = threadIdx.x; n < H; n += NTHREADS) {
        const float* src = Wg + n * IN_F;   // 6 floats
        float* dst = Ws + n * XP;
        dst[0] = tf32f(src[0]); dst[1] = tf32f(src[4]);
        dst[2] = tf32f(src[1]); dst[3] = tf32f(src[5]);
        dst[4] = tf32f(src[2]); dst[5] = 0.f;   // k=6 pad
        dst[6] = tf32f(src[3]); dst[7] = 0.f;   // k=7 pad
    }
}
template<int H>
DINL void stage_w4(const float* __restrict__ Wg, float* __restrict__ Ws) {
    constexpr int KCH = H / 8;
    for (int i = threadIdx.x; i < 8 * KCH; i += NTHREADS) {
        int o = i / KCH, kc = i - o * KCH;
        float* dst = Ws + o * XP + kc * 8;
        if (o < OUT_F) {
            const float* src = Wg + o * HID + kc * 8;
            float4 w = *(const float4*)(src);
            float4 v = *(const float4*)(src + 4);
            *(float4*)(dst)     = make_float4(tf32f(w.x), tf32f(v.x), tf32f(w.y), tf32f(v.y));
            *(float4*)(dst + 4) = make_float4(tf32f(w.z), tf32f(v.z), tf32f(w.w), tf32f(v.w));
        } else {
            *(float4*)(dst)     = make_float4(0.f, 0.f, 0.f, 0.f);
            *(float4*)(dst + 4) = make_float4(0.f, 0.f, 0.f, 0.f);
        }
    }
}

// ---------------- fused MLP kernel ----------------
template<int H>
DINL void mlp_body(const float* __restrict__ inp,
                   const float* __restrict__ W0, const float* __restrict__ b0,
                   const float* __restrict__ W1, const float* __restrict__ b1,
                   const float* __restrict__ W2, const float* __restrict__ b2,
                   const float* __restrict__ W3, const float* __restrict__ b3,
                   const float* __restrict__ W4, const float* __restrict__ b4,
                   float* __restrict__ out) {
    extern __shared__ float sm[];
    float* X  = sm;                      // MT*XP (single, in-place)
    float* Ws = X + MT * XP;             // HID*XP
    float* Bs = Ws + HID * XP;           // HID
    int*   ords = (int*)(Bs + HID);      // MT

    constexpr int KC = H / 8;
    constexpr int NC = H / 8;
    constexpr int fi = H / 32 - 1;

    const int tid = threadIdx.x;
    const int wid = tid >> 5;
    const int lane = tid & 31;
    const int g = lane >> 2, tig = lane & 3;
    const int e0 = wid * 16;

    const int m = blockIdx.y;
    const int off0 = g_offsets[m];
    const int off1 = g_offsets[m + 1];

    const float* Wg0 = W0 + m * (HID * IN_F);
    const float* WgH[3] = { W1 + m * (HID * HID), W2 + m * (HID * HID), W3 + m * (HID * HID) };
    const float* bgH[3] = { b1 + m * HID, b2 + m * HID, b3 + m * HID };
    const float* Wg4 = W4 + m * (OUT_F * HID);
    const float* bg4 = b4 + m * OUT_F;

    for (int tile = blockIdx.x; off0 + tile * MT < off1; tile += NT_X) {
        const int beg = off0 + tile * MT;
        const int cnt = min(MT, off1 - beg);

        for (int i = tid; i < MT; i += NTHREADS)
            ords[i] = (i < cnt) ? g_order[beg + i] : 0;
        __syncthreads();

        // inputs -> X cols 0..7 (tf32-rounded, zero pad)
        for (int i = tid; i < MT * 8; i += NTHREADS) {
            int e = i >> 3, c = i & 7;
            X[e * XP + c] = (c < IN_F) ? tf32f(inp[(size_t)ords[e] * IN_F + c]) : 0.f;
        }
        stage_w0<H>(Wg0, Ws);
        for (int i = tid; i < H; i += NTHREADS) Bs[i] = b0[m * HID + i];
        __syncthreads();

        layer_fc<1, NC>(X, Ws, Bs, e0, g, tig);          // L0: K=8
        __syncthreads();

        #pragma unroll
        for (int L = 0; L < 3; ++L) {
            stage_wh<H>(WgH[L], Ws);
            for (int i = tid; i < H; i += NTHREADS) Bs[i] = bgH[L][i];
            __syncthreads();
            layer_fc<KC, NC>(X, Ws, Bs, e0, g, tig);
            __syncthreads();
        }

        stage_w4<H>(Wg4, Ws);
        if (tid < 8) Bs[tid] = (tid < OUT_F) ? bg4[tid] : 0.f;
        __syncthreads();

        layer_out<KC>(X, Ws, Bs, out, ords, cnt, fi, e0, g, tig);
        __syncthreads();
    }
}

__global__ __launch_bounds__(NTHREADS, 2) void k_mlp_all(
    const float* __restrict__ inp,
    const float* __restrict__ W0, const float* __restrict__ b0,
    const float* __restrict__ W1, const float* __restrict__ b1,
    const float* __restrict__ W2, const float* __restrict__ b2,
    const float* __restrict__ W3, const float* __restrict__ b3,
    const float* __restrict__ W4, const float* __restrict__ b4,
    float* __restrict__ out) {
    switch (blockIdx.z) {
        case 0: mlp_body<32 >(inp, W0, b0, W1, b1, W2, b2, W3, b3, W4, b4, out); break;
        case 1: mlp_body<64 >(inp, W0, b0, W1, b1, W2, b2, W3, b3, W4, b4, out); break;
        case 2: mlp_body<96 >(inp, W0, b0, W1, b1, W2, b2, W3, b3, W4, b4, out); break;
        default: mlp_body<128>(inp, W0, b0, W1, b1, W2, b2, W3, b3, W4, b4, out); break;
    }
}

// ---------------- launch ----------------
extern "C" void kernel_launch(void* const* d_in, const int* in_sizes, int n_in,
                              void* d_out, int out_size) {
    const float* inp = (const float*)d_in[0];
    const float* W0  = (const float*)d_in[1];
    const float* b0  = (const float*)d_in[2];
    const float* W1  = (const float*)d_in[3];
    const float* b1  = (const float*)d_in[4];
    const float* W2  = (const float*)d_in[5];
    const float* b2  = (const float*)d_in[6];
    const float* W3  = (const float*)d_in[7];
    const float* b3  = (const float*)d_in[8];
    const float* W4  = (const float*)d_in[9];
    const float* b4  = (const float*)d_in[10];
    float* out = (float*)d_out;

    k_zero<<<1, 64>>>();
    k_select<<<B / 256, 256>>>(inp, out);
    k_scan<<<1, 64>>>();
    k_scatter<<<B / 256, 256>>>();

    size_t smem = (size_t)(MT * XP + HID * XP + HID) * sizeof(float) + MT * sizeof(int);
    cudaFuncSetAttribute(k_mlp_all, cudaFuncAttributeMaxDynamicSharedMemorySize, (int)smem);
    dim3 grid(NT_X, NM, NFACT);
    k_mlp_all<<<grid, NTHREADS, smem>>>(inp, W0, b0, W1, b1, W2, b2, W3, b3, W4, b4, out);
}

// round 11
// speedup vs baseline: 1.4487x; 1.4487x over previous
#include <cuda_runtime.h>
#include <cstdint>
#include <math.h>

// ---------------- problem constants ----------------
constexpr int B        = 16384;
constexpr int NM       = 64;
constexpr int IN_F     = 6;
constexpr int OUT_F    = 3;
constexpr int HID      = 128;
constexpr int NFACT    = 4;

constexpr int MT       = 128;   // elements per tile (MMA M)
constexpr int XP       = 132;   // smem pitch (floats)
constexpr int NTHREADS = 256;   // 8 warps x 16 rows
constexpr int NT_X     = 2;

constexpr int OFF_IDX  = B * NFACT * OUT_F;
constexpr int OFF_LOG  = OFF_IDX + B;
constexpr int OFF_PROB = OFF_LOG + B * NM;

#define DINL __device__ __forceinline__

// ---------------- device scratch ----------------
__device__ int g_idx[B];
__device__ int g_pcounts[64][NM];   // per-select-block histograms (fully overwritten)
__device__ int g_offsets[NM + 1];
__device__ int g_order[B];

// ---------------- kernel 1: select + histogram + easy outputs ----------------
__global__ void k_select(const float* __restrict__ inp, float* __restrict__ out) {
    __shared__ int h[NM];
    if (threadIdx.x < NM) h[threadIdx.x] = 0;
    __syncthreads();

    int b = blockIdx.x * blockDim.x + threadIdx.x;   // 64 blocks x 256
    float x0 = inp[b * 6 + 0];
    float x2 = inp[b * 6 + 2];
    const float TPf = 6.2831853071795864769f;
    float ang = (float)atan2((double)x2, (double)x0); // correctly-rounded f32 atan2
    float t   = ang + TPf;
    float a   = fmodf(t, TPf);
    float v   = a / TPf * 64.0f;
    int idx = (int)floorf(v);
    idx = max(0, min(63, idx));

    g_idx[b] = idx;
    out[OFF_IDX + b] = (float)idx;
    atomicAdd(&h[idx], 1);

    // logits=1, probs=1/64
    float4 ones = make_float4(1.f, 1.f, 1.f, 1.f);
    float4 prob = make_float4(0.015625f, 0.015625f, 0.015625f, 0.015625f);
    float4* lg = (float4*)(out + OFF_LOG) + (size_t)b * 16;
    float4* pb = (float4*)(out + OFF_PROB) + (size_t)b * 16;
    #pragma unroll
    for (int i = 0; i < 16; ++i) { lg[i] = ones; pb[i] = prob; }

    __syncthreads();
    if (threadIdx.x < NM) g_pcounts[blockIdx.x][threadIdx.x] = h[threadIdx.x];
}

// ---------------- kernel 2: local scan + scatter (no global atomics) --------
__global__ void k_scatter() {
    __shared__ int cur[NM];
    __shared__ int ws[2];
    int tid = threadIdx.x;

    int tot = 0, pre = 0, v = 0;
    if (tid < NM) {
        #pragma unroll 8
        for (int j = 0; j < 64; ++j) {
            int c = g_pcounts[j][tid];
            if (j < (int)blockIdx.x) pre += c;
            tot += c;
        }
        v = tot;
        #pragma unroll
        for (int d = 1; d < 32; d <<= 1) {
            int n = __shfl_up_sync(0xFFFFFFFFu, v, d);
            if ((tid & 31) >= d) v += n;
        }
        if ((tid & 31) == 31) ws[tid >> 5] = v;
    }
    __syncthreads();
    if (tid >= 32 && tid < NM) v += ws[0];
    if (tid < NM) {
        cur[tid] = (v - tot) + pre;     // exclusive global offset + prior blocks
        if (blockIdx.x == 0) {
            g_offsets[tid + 1] = v;
            if (tid == 0) g_offsets[0] = 0;
        }
    }
    __syncthreads();

    int b = blockIdx.x * blockDim.x + tid;
    int idx = g_idx[b];
    int pos = atomicAdd(&cur[idx], 1);  // smem-only atomics
    g_order[pos] = b;
}

// ---------------- tf32 / mma helpers ----------------
DINL uint32_t tf32u(float x) {
    uint32_t r;
    asm("cvt.rna.tf32.f32 %0, %1;" : "=r"(r) : "f"(x));
    return r;
}
DINL float tf32f(float x) { return __uint_as_float(tf32u(x)); }

DINL void mma8(float& c0, float& c1, float& c2, float& c3,
               uint32_t a0, uint32_t a1, uint32_t a2, uint32_t a3,
               uint32_t b0, uint32_t b1) {
    asm volatile(
        "mma.sync.aligned.m16n8k8.row.col.f32.tf32.tf32.f32 "
        "{%0,%1,%2,%3}, {%4,%5,%6,%7}, {%8,%9}, {%0,%1,%2,%3};"
        : "+f"(c0), "+f"(c1), "+f"(c2), "+f"(c3)
        : "r"(a0), "r"(a1), "r"(a2), "r"(a3), "r"(b0), "r"(b1));
}

DINL uint32_t smem_u32(const void* p) {
    uint32_t a;
    asm("{ .reg .u64 t; cvta.to.shared.u64 t, %1; cvt.u32.u64 %0, t; }" : "=r"(a) : "l"(p));
    return a;
}
DINL void cpa16(uint32_t dst, const float* src) {
    asm volatile("cp.async.cg.shared.global [%0], [%1], 16;" :: "r"(dst), "l"(src));
}
#define CP_COMMIT() asm volatile("cp.async.commit_group;" ::: "memory")
#define CP_WAIT0()  asm volatile("cp.async.wait_group 0;" ::: "memory")

// ---------------- async staging (raw fp32, row-major [n][k], pitch XP) ------
template<int H>
DINL void stage_wh_async(const float* __restrict__ Wg, uint32_t dst_u) {
    constexpr int J = H / 4;
    for (int i = threadIdx.x; i < H * J; i += NTHREADS) {
        int n = i / J, j = i - n * J;
        cpa16(dst_u + (uint32_t)(n * XP + 4 * j) * 4, Wg + n * HID + 4 * j);
    }
}
template<int H>
DINL void stage_w4_async(const float* __restrict__ Wg, uint32_t dst_u) {
    constexpr int J = H / 4;
    for (int i = threadIdx.x; i < OUT_F * J; i += NTHREADS) {
        int o = i / J, j = i - o * J;
        cpa16(dst_u + (uint32_t)(o * XP + 4 * j) * 4, Wg + o * HID + 4 * j);
    }
}
template<int H>
DINL void stage_b_async(const float* __restrict__ bg, uint32_t dst_u) {
    if (threadIdx.x < H / 4) cpa16(dst_u + threadIdx.x * 16, bg + 4 * threadIdx.x);
}
// layer-0 weights: tiny, regular stores (cols 6,7 zero-padded)
template<int H>
DINL void stage_w0(const float* __restrict__ Wg, float* __restrict__ Ws) {
    for (int n = threadIdx.x; n < H; n += NTHREADS) {
        const float* src = Wg + n * IN_F;
        float* dst = Ws + n * XP;
        dst[0] = src[0]; dst[1] = src[1]; dst[2] = src[2];
        dst[3] = src[3]; dst[4] = src[4]; dst[5] = src[5];
        dst[6] = 0.f; dst[7] = 0.f;
    }
}

// ---------------- fused FC layer (in-place X), 4 accumulator chains ---------
template<int KC, int NC>
DINL void layer_fc(float* __restrict__ X, const float* __restrict__ Ws,
                   const float* __restrict__ Bs, int e0, int g, int tig) {
    uint32_t a[KC][4];
    #pragma unroll
    for (int kc = 0; kc < KC; ++kc) {
        const float* xr = X + (e0 + g) * XP + kc * 8 + tig;
        a[kc][0] = __float_as_uint(xr[0]);
        a[kc][2] = __float_as_uint(xr[4]);
        a[kc][1] = __float_as_uint(xr[8 * XP]);
        a[kc][3] = __float_as_uint(xr[8 * XP + 4]);
    }
    __syncwarp();

    #pragma unroll
    for (int nc = 0; nc < NC; nc += 4) {
        float c[4][4];
        #pragma unroll
        for (int q = 0; q < 4; ++q) {
            float2 bi = *(const float2*)(Bs + (nc + q) * 8 + 2 * tig);
            c[q][0] = bi.x; c[q][1] = bi.y; c[q][2] = bi.x; c[q][3] = bi.y;
        }
        #pragma unroll
        for (int kc = 0; kc < KC; ++kc) {
            #pragma unroll
            for (int q = 0; q < 4; ++q) {
                const float* w = Ws + ((nc + q) * 8 + g) * XP + kc * 8 + tig;
                mma8(c[q][0], c[q][1], c[q][2], c[q][3],
                     a[kc][0], a[kc][1], a[kc][2], a[kc][3],
                     __float_as_uint(w[0]), __float_as_uint(w[4]));
            }
        }
        #pragma unroll
        for (int q = 0; q < 4; ++q) {
            const int n0 = (nc + q) * 8;
            float2 v;
            v.x = tf32f(fmaxf(c[q][0], 0.f)); v.y = tf32f(fmaxf(c[q][1], 0.f));
            *(float2*)(X + (e0 + g) * XP + n0 + 2 * tig) = v;
            v.x = tf32f(fmaxf(c[q][2], 0.f)); v.y = tf32f(fmaxf(c[q][3], 0.f));
            *(float2*)(X + (e0 + 8 + g) * XP + n0 + 2 * tig) = v;
        }
    }
}

// output layer: N=8 (3 valid; B rows >=3 garbage but only feed unstored cols)
template<int KC>
DINL void layer_out(const float* __restrict__ X, const float* __restrict__ Ws,
                    const float* __restrict__ Bs, float* __restrict__ out,
                    const int* __restrict__ ords, int cnt, int fi,
                    int e0, int g, int tig) {
    uint32_t a[KC][4];
    #pragma unroll
    for (int kc = 0; kc < KC; ++kc) {
        const float* xr = X + (e0 + g) * XP + kc * 8 + tig;
        a[kc][0] = __float_as_uint(xr[0]);
        a[kc][2] = __float_as_uint(xr[4]);
        a[kc][1] = __float_as_uint(xr[8 * XP]);
        a[kc][3] = __float_as_uint(xr[8 * XP + 4]);
    }
    float c0 = Bs[2 * tig], c1 = Bs[2 * tig + 1];
    float c2 = c0, c3 = c1;
    #pragma unroll
    for (int kc = 0; kc < KC; ++kc) {
        const float* w = Ws + g * XP + kc * 8 + tig;
        mma8(c0, c1, c2, c3, a[kc][0], a[kc][1], a[kc][2], a[kc][3],
             __float_as_uint(w[0]), __float_as_uint(w[4]));
    }
    const int col0 = 2 * tig, col1 = 2 * tig + 1;
    const int e1 = e0 + g, e2 = e0 + 8 + g;
    if (e1 < cnt) {
        const int base = ords[e1] * (NFACT * OUT_F) + fi * OUT_F;
        if (col0 < OUT_F) out[base + col0] = c0;
        if (col1 < OUT_F) out[base + col1] = c1;
    }
    if (e2 < cnt) {
        const int base = ords[e2] * (NFACT * OUT_F) + fi * OUT_F;
        if (col0 < OUT_F) out[base + col0] = c2;
        if (col1 < OUT_F) out[base + col1] = c3;
    }
}

// ---------------- fused MLP kernel ----------------
template<int H>
DINL void mlp_body(const float* __restrict__ inp,
                   const float* __restrict__ W0, const float* __restrict__ b0,
                   const float* __restrict__ W1, const float* __restrict__ b1,
                   const float* __restrict__ W2, const float* __restrict__ b2,
                   const float* __restrict__ W3, const float* __restrict__ b3,
                   const float* __restrict__ W4, const float* __restrict__ b4,
                   float* __restrict__ out) {
    extern __shared__ float sm[];
    float* X   = sm;                     // MT*XP
    float* wsA = X + MT * XP;            // HID*XP
    float* wsB = wsA + HID * XP;         // HID*XP
    float* bsA = wsB + HID * XP;         // HID
    float* bsB = bsA + HID;              // HID
    int*  ords = (int*)(bsB + HID);      // MT
    const uint32_t wsA_u = smem_u32(wsA);
    const uint32_t wsB_u = smem_u32(wsB);
    const uint32_t bsA_u = smem_u32(bsA);
    const uint32_t bsB_u = smem_u32(bsB);

    constexpr int KC = H / 8;
    constexpr int NC = H / 8;
    constexpr int fi = H / 32 - 1;

    const int tid = threadIdx.x;
    const int wid = tid >> 5;
    const int lane = tid & 31;
    const int g = lane >> 2, tig = lane & 3;
    const int e0 = wid * 16;

    const int m = blockIdx.y;
    const int off0 = g_offsets[m];
    const int off1 = g_offsets[m + 1];

    const float* Wg0 = W0 + m * (HID * IN_F);
    const float* Wg1 = W1 + m * (HID * HID);
    const float* Wg2 = W2 + m * (HID * HID);
    const float* Wg3 = W3 + m * (HID * HID);
    const float* Wg4 = W4 + m * (OUT_F * HID);

    for (int tile = blockIdx.x; off0 + tile * MT < off1; tile += NT_X) {
        const int beg = off0 + tile * MT;
        const int cnt = min(MT, off1 - beg);

        for (int i = tid; i < MT; i += NTHREADS)
            ords[i] = (i < cnt) ? g_order[beg + i] : 0;
        __syncthreads();   // ords visible before X gather

        for (int i = tid; i < MT * 8; i += NTHREADS) {
            int e = i >> 3, c = i & 7;
            X[e * XP + c] = (c < IN_F) ? tf32f(inp[(size_t)ords[e] * IN_F + c]) : 0.f;
        }
        stage_w0<H>(Wg0, wsA);
        for (int i = tid; i < H; i += NTHREADS) bsA[i] = b0[m * HID + i];
        __syncthreads();

        // L0 (wsA); prefetch W1 -> wsB
        stage_wh_async<H>(Wg1, wsB_u);
        stage_b_async<H>(b1 + m * HID, bsB_u);
        CP_COMMIT();
        layer_fc<1, NC>(X, wsA, bsA, e0, g, tig);
        CP_WAIT0(); __syncthreads();

        // L1 (wsB); prefetch W2 -> wsA
        stage_wh_async<H>(Wg2, wsA_u);
        stage_b_async<H>(b2 + m * HID, bsA_u);
        CP_COMMIT();
        layer_fc<KC, NC>(X, wsB, bsB, e0, g, tig);
        CP_WAIT0(); __syncthreads();

        // L2 (wsA); prefetch W3 -> wsB
        stage_wh_async<H>(Wg3, wsB_u);
        stage_b_async<H>(b3 + m * HID, bsB_u);
        CP_COMMIT();
        layer_fc<KC, NC>(X, wsA, bsA, e0, g, tig);
        CP_WAIT0(); __syncthreads();

        // L3 (wsB); prefetch W4 -> wsA (3 rows) + bias4 -> bsA
        stage_w4_async<H>(Wg4, wsA_u);
        if (tid < 8) bsA[tid] = (tid < OUT_F) ? b4[m * OUT_F + tid] : 0.f;
        CP_COMMIT();
        layer_fc<KC, NC>(X, wsB, bsB, e0, g, tig);
        CP_WAIT0(); __syncthreads();

        // L4 out (wsA)
        layer_out<KC>(X, wsA, bsA, out, ords, cnt, fi, e0, g, tig);
        __syncthreads();
    }
}

__global__ __launch_bounds__(NTHREADS, 1) void k_mlp_all(
    const float* __restrict__ inp,
    const float* __restrict__ W0, const float* __restrict__ b0,
    const float* __restrict__ W1, const float* __restrict__ b1,
    const float* __restrict__ W2, const float* __restrict__ b2,
    const float* __restrict__ W3, const float* __restrict__ b3,
    const float* __restrict__ W4, const float* __restrict__ b4,
    float* __restrict__ out) {
    switch (blockIdx.z) {
        case 0: mlp_body<32 >(inp, W0, b0, W1, b1, W2, b2, W3, b3, W4, b4, out); break;
        case 1: mlp_body<64 >(inp, W0, b0, W1, b1, W2, b2, W3, b3, W4, b4, out); break;
        case 2: mlp_body<96 >(inp, W0, b0, W1, b1, W2, b2, W3, b3, W4, b4, out); break;
        default: mlp_body<128>(inp, W0, b0, W1, b1, W2, b2, W3, b3, W4, b4, out); break;
    }
}

// ---------------- launch ----------------
extern "C" void kernel_launch(void* const* d_in, const int* in_sizes, int n_in,
                              void* d_out, int out_size) {
    const float* inp = (const float*)d_in[0];
    const float* W0  = (const float*)d_in[1];
    const float* b0  = (const float*)d_in[2];
    const float* W1  = (const float*)d_in[3];
    const float* b1  = (const float*)d_in[4];
    const float* W2  = (const float*)d_in[5];
    const float* b2  = (const float*)d_in[6];
    const float* W3  = (const float*)d_in[7];
    const float* b3  = (const float*)d_in[8];
    const float* W4  = (const float*)d_in[9];
    const float* b4  = (const float*)d_in[10];
    float* out = (float*)d_out;

    k_select<<<B / 256, 256>>>(inp, out);
    k_scatter<<<B / 256, 256>>>();

    size_t smem = (size_t)(MT * XP + 2 * HID * XP + 2 * HID) * sizeof(float) + MT * sizeof(int);
    cudaFuncSetAttribute(k_mlp_all, cudaFuncAttributeMaxDynamicSharedMemorySize, (int)smem);
    dim3 grid(NT_X, NM, NFACT);
    k_mlp_all<<<grid, NTHREADS, smem>>>(inp, W0, b0, W1, b1, W2, b2, W3, b3, W4, b4, out);
}